// round 17
// baseline (speedup 1.0000x reference)
#include <cuda_runtime.h>
#include <cuda_fp16.h>
#include <cstdint>

// MeshConvPoint via warp-level mma.sync (fp16 HMMA, single-pass).
//   out[pts,128] = G[pts,448] @ W[448,128] + bias, fused with gather.
//   fp16 operands, fp32 accumulation: rel_err ~2.9e-4 global-norm.
//
// R16: persistent n-split CTAs with RESIDENT B.
//   task = (tile of 64 points) x (n-half of 64 outputs); NTASK = 6250.
//   grid = 296 persistent CTAs (2/SM at 109KB smem), each loops ~21 tasks.
//   B (this CTA's 64-output half, all 4 K-chunks, 61.4KB) loaded ONCE per
//   CTA -> per-tile B L2 traffic eliminated (was 384MB total).
//   8 warps of m32n16; A double-buffered; one syncthreads per chunk;
//   next task's gather(0) prefetched during chunk 3.

#define BATCH    4
#define CIN      64
#define NV       50000
#define COUT     128
#define NK       7
#define CK       (CIN * NK)              // 448
#define NPTS     (BATCH * NV)            // 200000
#define TP       64                      // points per tile
#define NOUTH    64                      // outputs per CTA (n-half)
#define NTASK    ((NPTS / TP) * 2)       // 6250
#define NTHREADS 256
#define NCTA     296                     // 2 per SM x 148
#define NCHUNK   4
#define KCHUNK   112
#define ROWB     240                     // row bytes = 120 fp16 (112 data + 8 pad)
#define TILE_A   (TP * ROWB)             // 15360
#define TILE_BC  (NOUTH * ROWB)          // 15360 per B chunk

// smem layout (bytes)
#define OFF_B    0                        // [4 chunk][TILE_BC] = 61440 RESIDENT
#define OFF_A    (4 * TILE_BC)            // 61440: [2 stage][TILE_A] = 30720
#define OFF_GRAW (OFF_A + 2 * TILE_A)     // 92160: [4][256][16] = 16384
#define OFF_BIAS (OFF_GRAW + 16384)       // 108544: 64 floats
#define SMEM_TOTAL (OFF_BIAS + 512)       // 109056
#define SOUT_PITCH 120                    // overlay [64][120] f32 = 30720 = A region exactly

// static scratch
__device__ __align__(16) float  g_xT[(size_t)BATCH * NV * CIN];   // 51.2 MB
__device__ __align__(16) __half g_Whf[NCHUNK][128][120];          // fp16 W tiles

__device__ __forceinline__ uint32_t smem_u32(const void* p) {
    uint32_t a;
    asm("{ .reg .u64 t; cvta.to.shared.u64 t, %1; cvt.u32.u64 %0, t; }" : "=r"(a) : "l"(p));
    return a;
}
__device__ __forceinline__ uint32_t pack_f16x2(float hi, float lo) {
    uint32_t d;
    asm("cvt.rn.f16x2.f32 %0, %1, %2;" : "=r"(d) : "f"(hi), "f"(lo));
    return d;
}

#define LDMX4(r0, r1, r2, r3, addr) \
    asm volatile("ldmatrix.sync.aligned.m8n8.x4.shared.b16 {%0,%1,%2,%3}, [%4];" \
                 : "=r"(r0), "=r"(r1), "=r"(r2), "=r"(r3) : "r"(addr))

#define MMA16816(d, a0, a1, a2, a3, b0, b1) \
    asm volatile("mma.sync.aligned.m16n8k16.row.col.f32.f16.f16.f32 " \
                 "{%0,%1,%2,%3}, {%4,%5,%6,%7}, {%8,%9}, {%0,%1,%2,%3};" \
                 : "+f"((d)[0]), "+f"((d)[1]), "+f"((d)[2]), "+f"((d)[3]) \
                 : "r"(a0), "r"(a1), "r"(a2), "r"(a3), "r"(b0), "r"(b1))

#define CPA16(dst, src, sz) \
    asm volatile("cp.async.cg.shared.global [%0], [%1], 16, %2;" \
                 :: "r"(dst), "l"(src), "r"(sz))
#define CPCOMMIT() asm volatile("cp.async.commit_group;" ::: "memory")
#define CPWAIT0()  asm volatile("cp.async.wait_group 0;" ::: "memory")

// ---- 1) transpose x [B,C,V] -> xT [B,V,C], float4 both sides ----
__global__ void transpose_kernel(const float* __restrict__ x) {
    __shared__ float tile[64][68];       // 68 pad: 16B-aligned cols, conflict-free read
    const int b  = blockIdx.y;
    const int vb = blockIdx.x * 64;
    const int t  = threadIdx.x;          // 256

    // load: thread -> (c = t>>2, seg = t&3); 16 consecutive v per thread
    {
        const int c  = t >> 2;
        const int v0 = vb + (t & 3) * 16;
        if (v0 < NV) {                   // NV % 16 == 0: window all-valid or none
            const float4* src = (const float4*)&x[((size_t)(b * CIN + c)) * NV + v0];
#pragma unroll
            for (int k = 0; k < 4; k++) {
                float4 w = src[k];
                *(float4*)&tile[c][(t & 3) * 16 + 4 * k] = w;
            }
        }
    }
    __syncthreads();

    // store: thread -> (vloc = t&63, cgroup = t>>6); 16 consecutive c per thread
    {
        const int vloc = t & 63;
        const int c0   = (t >> 6) * 16;
        const int v    = vb + vloc;
        if (v < NV) {
            float* dst = &g_xT[((size_t)(b * NV + v)) * CIN + c0];
#pragma unroll
            for (int k = 0; k < 4; k++) {
                float4 w = make_float4(tile[c0 + 4 * k][vloc], tile[c0 + 4 * k + 1][vloc],
                                       tile[c0 + 4 * k + 2][vloc], tile[c0 + 4 * k + 3][vloc]);
                *(float4*)&dst[4 * k] = w;
            }
        }
    }
}

// ---- 2) W -> fp16 tiles [chunk][n=128][k=120], k = r*16 + c ----
__global__ void wprep_kernel(const float* __restrict__ W) {
    int i = blockIdx.x * 256 + threadIdx.x;         // over 4*128*120 = 61440
    if (i >= NCHUNK * 128 * 120) return;
    int kl = i % 120;
    int n  = (i / 120) & 127;
    int ch = i / (120 * 128);
    float v = 0.0f;
    if (kl < KCHUNK) {
        int r = kl >> 4, c = kl & 15;
        v = W[n * CK + (ch * 16 + c) * NK + r];
    }
    g_Whf[ch][n][kl] = __float2half_rn(v);
}

// ---- 3) persistent fused main kernel (occupancy 2) ----
__global__ void __launch_bounds__(NTHREADS, 2)
mesh_main(const int* __restrict__ Gi32,
          const float* __restrict__ bias,
          float* __restrict__ out) {
    extern __shared__ char sm[];
    const uint32_t sb = smem_u32(sm);
    const int t    = threadIdx.x;
    const int wid  = t >> 5;
    const int lane = t & 31;

    // first task decides this CTA's n-half; all its tasks share nh parity?
    // task ids stride by gridDim.x (296, even) -> nh = task&1 is CONSTANT per CTA.
    const int nh = blockIdx.x & 1;

    float* sBias = (float*)(sm + OFF_BIAS);
    if (t < NOUTH) sBias[t] = bias[nh * NOUTH + t];

    // one-time B load: this n-half of all 4 chunks (61440B)
    {
        const char* bsrc = (const char*)&g_Whf[0][0][0];
        // chunk ch rows [nh*64, nh*64+64) = contiguous 15360B at offset
        for (int ch = 0; ch < NCHUNK; ch++) {
            const char* src = (const char*)&g_Whf[ch][nh * NOUTH][0];
            const uint32_t dst = sb + OFF_B + (uint32_t)ch * TILE_BC;
            for (int i = t; i < TILE_BC / 16; i += NTHREADS)
                CPA16(dst + (uint32_t)i * 16, src + (size_t)i * 16, 16u);
        }
        CPCOMMIT();
        (void)bsrc;
    }

    // per-thread gather task: point gp (0..63), 4-channel group gq (0..3)
    const int gp = t >> 2, gq = t & 3;
    const bool is64 = ((Gi32[1] | Gi32[3] | Gi32[5] | Gi32[7]) == 0);

    // warp MMA tiling: 2(m) x 4(n) warps of m32 x n16
    const int mb = (wid & 1) * 32;
    const int nb = (wid >> 1) * 16;
    const int mi = lane >> 3, rowin = lane & 7;
    const uint32_t aOff = (uint32_t)(mb + (mi & 1) * 8 + rowin) * ROWB + (uint32_t)(mi >> 1) * 16;
    const uint32_t bOff = (uint32_t)(nb + (mi >> 1) * 8 + rowin) * ROWB + (uint32_t)(mi & 1) * 16;

    // resolve rows for a task; invalid task -> all -1
    auto resolve = [&](long long task, int* r) {
#pragma unroll
        for (int j = 0; j < 4; j++) r[j] = -1;
        if (task >= NTASK) return;
        int tile = (int)(task >> 1);
        int pg = tile * TP + gp;
        int base = (pg / NV) * NV;
#pragma unroll
        for (int j = 0; j < 4; j++) {
            int raw = is64 ? Gi32[2 * (pg * 4 + j)] : Gi32[pg * 4 + j];
            if (raw >= 0 && raw < NV) r[j] = base + raw;
        }
    };
    auto issue_gather = [&](const int* r, int ch) {
#pragma unroll
        for (int j = 0; j < 4; j++) {
            const char* src = (const char*)(g_xT +
                ((r[j] >= 0) ? (size_t)r[j] * CIN : 0) + (ch * 16 + gq * 4));
            CPA16(sb + OFF_GRAW + (uint32_t)(j * NTHREADS + t) * 16, src,
                  r[j] >= 0 ? 16u : 0u);
        }
        CPCOMMIT();
    };

    // features: staging -> fp16 A[stage]
    auto features = [&](int stage) {
        float4 v[4];
#pragma unroll
        for (int j = 0; j < 4; j++) {
            uint32_t a = sb + OFF_GRAW + (uint32_t)(j * NTHREADS + t) * 16;
            asm volatile("ld.shared.v4.f32 {%0,%1,%2,%3}, [%4];"
                         : "=f"(v[j].x), "=f"(v[j].y), "=f"(v[j].z), "=f"(v[j].w)
                         : "r"(a));
        }
        const float a0[4] = {v[0].x, v[0].y, v[0].z, v[0].w};
        const float a1[4] = {v[1].x, v[1].y, v[1].z, v[1].w};
        const float a2[4] = {v[2].x, v[2].y, v[2].z, v[2].w};
        const float a3[4] = {v[3].x, v[3].y, v[3].z, v[3].w};
        float sf[NK][4];
#pragma unroll
        for (int ci = 0; ci < 4; ci++) {
            float f0 = a0[ci], f1 = a1[ci], f2 = a2[ci], f3 = a3[ci];
            float p12 = f1 * f2, p13 = f1 * f3, p23 = f2 * f3;
            sf[0][ci] = f0;
            sf[1][ci] = f1 + f2 + f3;
            sf[2][ci] = p12 * f3;
            sf[3][ci] = p12 + p13 + p23;
            sf[4][ci] = f1 * f1 + f2 * f2 + f3 * f3;
            sf[5][ci] = fabsf(f1 - f2) + fabsf(f1 - f3) + fabsf(f2 - f3);
            sf[6][ci] = f1 * f1 * f1 + f2 * f2 * f2 + f3 * f3 * f3;
        }
        char* Ah = sm + OFF_A + stage * TILE_A + gp * ROWB + gq * 8;
#pragma unroll
        for (int r = 0; r < NK; r++) {
            uint32_t w0 = pack_f16x2(sf[r][1], sf[r][0]);
            uint32_t w1 = pack_f16x2(sf[r][3], sf[r][2]);
            *(uint2*)(Ah + r * 32) = make_uint2(w0, w1);
        }
    };

    // ---- task loop ----
    int rows[4], rowsN[4];
    long long task = blockIdx.x;
    resolve(task, rows);
    CPWAIT0();                 // B resident landed (and nothing else in flight)
    issue_gather(rows, 0);     // prologue gather for first task

    float* sOut = (float*)(sm + OFF_A);   // [64][SOUT_PITCH] overlay on A tiles

    for (; task < NTASK; task += gridDim.x) {
        float acc[2][2][4];
#pragma unroll
        for (int a = 0; a < 2; a++)
#pragma unroll
            for (int b = 0; b < 2; b++)
#pragma unroll
                for (int c = 0; c < 4; c++) acc[a][b][c] = 0.0f;

        for (int ch = 0; ch < NCHUNK; ch++) {
            const int stage = ch & 1;
            CPWAIT0();                     // gather(ch) landed
            features(stage);
            if (ch + 1 < NCHUNK) {
                issue_gather(rows, ch + 1);            // hides under MMA(ch)
            } else {
                resolve(task + gridDim.x, rowsN);      // next task (same nh)
                issue_gather(rowsN, 0);                // hides under MMA(3)+epilogue
            }
            __syncthreads();               // A[stage] visible; MMA(ch-1) done CTA-wide

            const uint32_t Ab = sb + OFF_A + (uint32_t)stage * TILE_A;
            const uint32_t Bb = sb + OFF_B + (uint32_t)ch * TILE_BC;
#pragma unroll
            for (int ks = 0; ks < 7; ks++) {
                const uint32_t kb = (uint32_t)ks * 32;
                uint32_t a0, a1, a2, a3, a4, a5, a6, a7;
                LDMX4(a0, a1, a2, a3, Ab + aOff + kb);
                LDMX4(a4, a5, a6, a7, Ab + aOff + 16 * ROWB + kb);
                uint32_t b0, b1, b2, b3;
                LDMX4(b0, b1, b2, b3, Bb + bOff + kb);

                MMA16816(acc[0][0], a0, a1, a2, a3, b0, b1);
                MMA16816(acc[0][1], a0, a1, a2, a3, b2, b3);
                MMA16816(acc[1][0], a4, a5, a6, a7, b0, b1);
                MMA16816(acc[1][1], a4, a5, a6, a7, b2, b3);
            }
        }
        __syncthreads();   // all MMA(3) done reading A before sOut overlay

        // epilogue: frags -> sOut[p][o_local], then coalesced global stores
        {
            const int r4 = lane >> 2, c2 = 2 * (lane & 3);
#pragma unroll
            for (int mt = 0; mt < 2; mt++) {
                const int prow = mb + mt * 16 + r4;
#pragma unroll
                for (int ng = 0; ng < 2; ng++) {
                    const int n = nb + ng * 8 + c2;
                    *(float2*)&sOut[prow * SOUT_PITCH + n] =
                        make_float2(acc[mt][ng][0], acc[mt][ng][1]);
                    *(float2*)&sOut[(prow + 8) * SOUT_PITCH + n] =
                        make_float2(acc[mt][ng][2], acc[mt][ng][3]);
                }
            }
        }
        __syncthreads();

        {
            const int tile = (int)(task >> 1);
            const int p0 = tile * TP;
            for (int idx = t; idx < NOUTH * TP; idx += NTHREADS) {
                int o  = idx >> 6;             // 0..63 local
                int vl = idx & 63;             // 0..63
                int pg = p0 + vl;
                int b = pg / NV;
                int v = pg - b * NV;
                out[((size_t)(b * COUT + nh * NOUTH + o)) * NV + v] =
                    sOut[vl * SOUT_PITCH + o] + sBias[o];
            }
        }
        __syncthreads();   // sOut reads done before next task's features overwrite

#pragma unroll
        for (int j = 0; j < 4; j++) rows[j] = rowsN[j];
    }
}

extern "C" void kernel_launch(void* const* d_in, const int* in_sizes, int n_in,
                              void* d_out, int out_size) {
    const float* x    = (const float*)d_in[0];      // [B, C_IN, V, 1]
    const int*   Gi   = (const int*)d_in[1];        // [B, V, 4] (int32/int64 probed)
    const float* W    = (const float*)d_in[2];      // [C_OUT, C_IN, 7]
    const float* bias = (const float*)d_in[3];      // [C_OUT]
    float*       out  = (float*)d_out;              // [B, C_OUT, V, 1]

    static bool attr_set = false;
    if (!attr_set) {
        cudaFuncSetAttribute(mesh_main,
                             cudaFuncAttributeMaxDynamicSharedMemorySize,
                             SMEM_TOTAL);
        attr_set = true;
    }

    transpose_kernel<<<dim3((NV + 63) / 64, BATCH), 256>>>(x);
    wprep_kernel<<<(NCHUNK * 128 * 120 + 255) / 256, 256>>>(W);
    mesh_main<<<NCTA, NTHREADS, SMEM_TOTAL>>>(Gi, bias, out);
}